// round 14
// baseline (speedup 1.0000x reference)
#include <cuda_runtime.h>
#include <cub/cub.cuh>
#include <cstdint>

namespace {
constexpr int BATCH = 8;
constexpr int NANCH = 262144;         // 2^18
constexpr int TOTAL = BATCH * NANCH;  // 2,097,152
constexpr int TOPK  = 6000;
constexpr int NOUT  = 1000;
constexpr int COLB  = (TOPK + 63) / 64;            // 94
constexpr float THR = 0.7f;
constexpr int TAIL_BITS = TOPK - (COLB - 1) * 64;  // 48
constexpr int HBINS = 32768;   // bucket = float_bits >> 15 (scores in (0,1))
constexpr int CAP   = 10240;   // per-batch candidate capacity (expected ~6500)
constexpr int SORT_THREADS = 1024;
constexpr int SORT_ITEMS   = CAP / SORT_THREADS;   // 10
constexpr int SWEEP_THREADS = 512;
constexpr int SWEEP_SMEM = TOPK * 8 + COLB * 8 + NOUT * 4 + 16;
constexpr int IOU_ROWS = 1024;         // rows per iou block (4 per thread)
}

// -------- device-global scratch (no allocation allowed) ----------------------
__device__ int                g_hist[BATCH * HBINS];
__device__ int                g_thresh[BATCH];
__device__ int                g_cnt[BATCH];
__device__ unsigned long long g_cand[BATCH * CAP];
__device__ __align__(16) float g_boxes[BATCH * TOPK * 4];
__device__ unsigned long long g_mask[(size_t)BATCH * TOPK * COLB];  // upper-tri valid
__device__ unsigned long long g_diag[BATCH * TOPK];

// -------- 1. per-batch histogram — 4 elements/thread (MLP=2) ------------------
__global__ void hist_kernel(const float4* __restrict__ cls4) {
    int t = blockIdx.x * blockDim.x + threadIdx.x;
    int e0 = t << 2;                         // 4 elements; never crosses a batch
    if (e0 >= TOTAL) return;
    float4 v0 = __ldg(&cls4[t * 2]);
    float4 v1 = __ldg(&cls4[t * 2 + 1]);     // scores at .y / .w (rpn_class[...,1])
    int* h = &g_hist[(e0 >> 18) * HBINS];
    atomicAdd(&h[__float_as_uint(v0.y) >> 15], 1);
    atomicAdd(&h[__float_as_uint(v0.w) >> 15], 1);
    atomicAdd(&h[__float_as_uint(v1.y) >> 15], 1);
    atomicAdd(&h[__float_as_uint(v1.w) >> 15], 1);
}

// -------- 2. threshold bucket: largest T with count(bucket >= T) >= TOPK -----
__global__ void thresh_kernel() {
    constexpr int BPT = HBINS / 256;
    int b = blockIdx.x;
    int t = threadIdx.x;
    __shared__ int lsum[256];
    __shared__ int suff[256];
    int base = b * HBINS + t * BPT;
    int s = 0;
    for (int i = 0; i < BPT; ++i) s += g_hist[base + i];
    lsum[t] = s;
    __syncthreads();
    if (t == 0) {
        int run = 0;
        for (int u = 255; u >= 0; --u) { suff[u] = run; run += lsum[u]; }
    }
    __syncthreads();
    int above = suff[t];
    if (above < TOPK && above + lsum[t] >= TOPK) {
        int run = above;
        for (int i = BPT - 1; i >= 0; --i) {
            run += g_hist[base + i];
            if (run >= TOPK) { g_thresh[b] = t * BPT + i; break; }
        }
    }
}

// -------- 3. compact candidates — threshold-rebased keys ----------------------
// key = (bits - T<<15) << 18 | (0x3FFFF - idx). Monotone shift of score bits:
// per-batch descending sort => desc score, ties by ascending index == top_k.
__global__ void compact_kernel(const float4* __restrict__ cls4) {
    int t = blockIdx.x * blockDim.x + threadIdx.x;
    int e0 = t << 2;
    if (e0 >= TOTAL) return;
    float4 v0 = __ldg(&cls4[t * 2]);
    float4 v1 = __ldg(&cls4[t * 2 + 1]);
    int b = e0 >> 18;
    unsigned Tb = (unsigned)__ldg(&g_thresh[b]) << 15;
    unsigned sc[4] = { __float_as_uint(v0.y), __float_as_uint(v0.w),
                       __float_as_uint(v1.y), __float_as_uint(v1.w) };
    #pragma unroll
    for (int i = 0; i < 4; ++i) {
        if (sc[i] >= Tb) {
            int pos = atomicAdd(&g_cnt[b], 1);
            if (pos < CAP)
                g_cand[b * CAP + pos] =
                    ((unsigned long long)(sc[i] - Tb) << 18) |
                    (unsigned long long)(0x3FFFF - ((e0 + i) & (NANCH - 1)));
        }
    }
}

// -------- 3b. per-batch sort + FUSED box decode --------------------------------
// After BlockRadixSort the top-TOPK keys live in registers (blocked layout):
// decode anchors+deltas here, skipping the g_sorted round trip + extra launch.
using BlockSortT = cub::BlockRadixSort<unsigned long long, SORT_THREADS, SORT_ITEMS>;
__global__ void __launch_bounds__(SORT_THREADS)
sort_boxes_kernel(const float* __restrict__ rpn_bbox,
                  const float* __restrict__ anchors) {
    extern __shared__ char sort_raw[];
    auto& ts = *reinterpret_cast<typename BlockSortT::TempStorage*>(sort_raw);
    int b = blockIdx.x;
    int cnt = min(g_cnt[b], CAP);
    int D = 32768 - g_thresh[b];           // rebased score' < D * 2^15
    int ebits = 33 + (32 - __clz(D | 1));  // 18 idx + 15 + bits(D)
    if (ebits > 48) ebits = 48;
    unsigned long long keys[SORT_ITEMS];
    #pragma unroll
    for (int k = 0; k < SORT_ITEMS; ++k) {
        int i = threadIdx.x * SORT_ITEMS + k;      // blocked arrangement
        keys[k] = (i < cnt) ? g_cand[b * CAP + i] : 0ull;  // 0 pads to tail
    }
    BlockSortT(ts).SortDescending(keys, 0, ebits);
    #pragma unroll
    for (int k = 0; k < SORT_ITEMS; ++k) {
        int i = threadIdx.x * SORT_ITEMS + k;
        if (i >= TOPK) continue;
        int idx = 0x3FFFF - (int)(keys[k] & 0x3FFFFull);
        int src = (b * NANCH + idx) * 4;
        float4 a = *reinterpret_cast<const float4*>(anchors  + src);
        float4 d = *reinterpret_cast<const float4*>(rpn_bbox + src);
        float dy = d.x * 0.1f, dx = d.y * 0.1f;
        float dh = d.z * 0.2f, dw = d.w * 0.2f;
        float h = a.z - a.x;
        float w = a.w - a.y;
        float cy = a.x + 0.5f * h;
        float cx = a.y + 0.5f * w;
        cy = cy + dy * h;
        cx = cx + dx * w;
        h = h * expf(dh);
        w = w * expf(dw);
        float y1 = fminf(fmaxf(cy - 0.5f * h, 0.f), 1.f);
        float x1 = fminf(fmaxf(cx - 0.5f * w, 0.f), 1.f);
        float y2 = fminf(fmaxf(cy + 0.5f * h, 0.f), 1.f);
        float x2 = fminf(fmaxf(cx + 0.5f * w, 0.f), 1.f);
        reinterpret_cast<float4*>(g_boxes)[b * TOPK + i] =
            make_float4(y1, x1, y2, x2);
    }
}

// -------- 4. pairwise IoU bitmask — compare-only pass 1, 4 rows/thread ---------
// Pass 1: 4-comparison interval-overlap test (superset of true overlap; equal
// except degenerate zero-extent boxes, which pass-2's exact IoU rejects).
// Pass 2: exact fp32 IoU on candidate bits only — bit-identical results.
__device__ __forceinline__ void iou_row(
    const float4* colBox, float4 rb, unsigned long long cand,
    unsigned long long* maskOut, unsigned long long* diagOut) {
    float area1 = (rb.z - rb.x) * (rb.w - rb.y);
    unsigned long long m = 0;
    while (cand) {
        int j = __ffsll((long long)cand) - 1;
        cand &= cand - 1;
        float4 cb = colBox[j];
        float y1 = fmaxf(rb.x, cb.x);
        float x1 = fmaxf(rb.y, cb.y);
        float y2 = fminf(rb.z, cb.z);
        float x2 = fminf(rb.w, cb.w);
        float inter = fmaxf(y2 - y1, 0.f) * fmaxf(x2 - x1, 0.f);
        float area2 = (cb.z - cb.x) * (cb.w - cb.y);
        float iou = inter / (area1 + area2 - inter + 1e-9f);
        if (iou > THR) m |= 1ull << j;
    }
    *maskOut = m;
    if (diagOut) *diagOut = m;
}

__global__ void iou_kernel() {
    int b = blockIdx.z;
    int C = blockIdx.x * 64;                 // column start
    int R = blockIdx.y * IOU_ROWS;           // row start
    if (R >= C + 64) return;                 // block fully below diagonal
    __shared__ float4 colBox[64];
    int tid = threadIdx.x;
    int ncols = min(64, TOPK - C);
    if (tid < ncols)
        colBox[tid] = reinterpret_cast<const float4*>(g_boxes)[b * TOPK + C + tid];
    __syncthreads();

    float4 rb[4];
    bool v[4];
    bool any = false;
    #pragma unroll
    for (int k = 0; k < 4; ++k) {
        int i = R + tid + (k << 8);
        v[k] = (i < TOPK) && (i < C + 64);
        any |= v[k];
        rb[k] = v[k] ? reinterpret_cast<const float4*>(g_boxes)[b * TOPK + i]
                     : make_float4(0.f, 0.f, 0.f, 0.f);
    }
    if (!any) return;

    unsigned lo[4] = {0, 0, 0, 0}, hi[4] = {0, 0, 0, 0};
    if (ncols == 64) {
        #pragma unroll
        for (int j = 0; j < 64; ++j) {
            float4 cb = colBox[j];
            #pragma unroll
            for (int k = 0; k < 4; ++k) {
                bool ov = (cb.z > rb[k].x) & (rb[k].z > cb.x) &
                          (cb.w > rb[k].y) & (rb[k].w > cb.y);
                if (j < 32) lo[k] |= ov ? (1u << j) : 0u;
                else        hi[k] |= ov ? (1u << (j - 32)) : 0u;
            }
        }
    } else {
        for (int j = 0; j < ncols; ++j) {
            float4 cb = colBox[j];
            #pragma unroll
            for (int k = 0; k < 4; ++k) {
                bool ov = (cb.z > rb[k].x) & (rb[k].z > cb.x) &
                          (cb.w > rb[k].y) & (rb[k].w > cb.y);
                if (j < 32) lo[k] |= ov ? (1u << j) : 0u;
                else        hi[k] |= ov ? (1u << (j - 32)) : 0u;
            }
        }
    }

    #pragma unroll
    for (int k = 0; k < 4; ++k) {
        if (!v[k]) continue;
        int i = R + tid + (k << 8);
        bool isDiag = ((i >> 6) == (C >> 6));
        unsigned long long* dout = isDiag ? &g_diag[b * TOPK + i] : nullptr;
        iou_row(colBox, rb[k],
                ((unsigned long long)hi[k] << 32) | lo[k],
                &g_mask[((size_t)(b * TOPK + i)) * COLB + blockIdx.x], dout);
    }
}

// -------- 5. sweep: smem chain (thread 0) + block-parallel batched row ORs -----
__global__ void __launch_bounds__(SWEEP_THREADS)
sweep_kernel(float* __restrict__ out) {
    extern __shared__ unsigned long long dsm[];
    unsigned long long* diag_sh = dsm;                 // TOPK u64 (48 KB)
    unsigned long long* rem_sh  = dsm + TOPK;          // COLB u64
    int* kept_sh = reinterpret_cast<int*>(rem_sh + COLB);  // NOUT ints
    int* ctrl    = kept_sh + NOUT;                     // [0]=m for this word

    int b = blockIdx.x;
    int tid = threadIdx.x;
    int warp = tid >> 5;
    int lane = tid & 31;
    constexpr int NWARP = SWEEP_THREADS / 32;

    for (int i = tid; i < TOPK; i += SWEEP_THREADS)
        diag_sh[i] = g_diag[b * TOPK + i];
    if (tid < COLB)
        rem_sh[tid] = (tid == COLB - 1) ? ~((1ull << TAIL_BITS) - 1ull) : 0ull;
    __syncthreads();

    int cnt = 0;
    for (int w = 0; w < COLB; ++w) {
        // Phase A (thread 0): resolve all kept bits of word w using smem only.
        if (tid == 0) {
            unsigned long long avail = ~rem_sh[w];
            int m = 0;
            while (avail && cnt + m < NOUT) {
                int bit = __ffsll((long long)avail) - 1;
                int i = (w << 6) + bit;
                kept_sh[cnt + m] = i;
                ++m;
                avail &= avail - 1;        // clear taken bit (zero-area safe)
                avail &= ~diag_sh[i];      // within-word forward suppression
            }
            ctrl[0] = m;
        }
        __syncthreads();
        int m = ctrl[0];
        // Phase B (whole block): OR the m kept rows into rem for words > w.
        for (int k = warp; k < m; k += NWARP) {
            const unsigned long long* row =
                &g_mask[((size_t)(b * TOPK + kept_sh[cnt + k])) * COLB];
            for (int ww = w + 1 + lane; ww < COLB; ww += 32)
                atomicOr(&rem_sh[ww], row[ww]);
        }
        cnt += m;
        if (cnt >= NOUT) break;           // uniform across block: safe
        __syncthreads();
    }
    __syncthreads();

    for (int k = tid; k < NOUT; k += SWEEP_THREADS) {
        float4 v = make_float4(0.f, 0.f, 0.f, 0.f);
        if (k < cnt)
            v = reinterpret_cast<const float4*>(g_boxes)[b * TOPK + kept_sh[k]];
        reinterpret_cast<float4*>(out)[b * NOUT + k] = v;
    }
}

// -------- launch --------------------------------------------------------------
extern "C" void kernel_launch(void* const* d_in, const int* in_sizes, int n_in,
                              void* d_out, int out_size) {
    const float* rpn_class = (const float*)d_in[0];
    const float* rpn_bbox  = (const float*)d_in[1];
    const float* anchors   = (const float*)d_in[2];
    float* out = (float*)d_out;

    void *histp, *cntp;
    cudaGetSymbolAddress(&histp, g_hist);
    cudaGetSymbolAddress(&cntp,  g_cnt);
    cudaMemsetAsync(histp, 0, sizeof(g_hist));
    cudaMemsetAsync(cntp,  0, sizeof(g_cnt));

    hist_kernel<<<TOTAL / 4 / 256, 256>>>((const float4*)rpn_class);
    thresh_kernel<<<BATCH, 256>>>();
    compact_kernel<<<TOTAL / 4 / 256, 256>>>((const float4*)rpn_class);

    constexpr int SORT_SMEM = (int)sizeof(typename BlockSortT::TempStorage);
    cudaFuncSetAttribute(sort_boxes_kernel,
                         cudaFuncAttributeMaxDynamicSharedMemorySize, SORT_SMEM);
    sort_boxes_kernel<<<BATCH, SORT_THREADS, SORT_SMEM>>>(rpn_bbox, anchors);

    dim3 gmask(COLB, (TOPK + IOU_ROWS - 1) / IOU_ROWS, BATCH);
    iou_kernel<<<gmask, 256>>>();

    cudaFuncSetAttribute(sweep_kernel,
                         cudaFuncAttributeMaxDynamicSharedMemorySize, SWEEP_SMEM);
    sweep_kernel<<<BATCH, SWEEP_THREADS, SWEEP_SMEM>>>(out);
}